// round 7
// baseline (speedup 1.0000x reference)
#include <cuda_runtime.h>
#include <cstdint>

#define N_IN    50000
#define C_DIM   64
#define T_DIM   8
#define E_EDGES 800000
#define N_OUT   50000
#define F_DIM   64
#define KDIM    512   // T*C

#define SCAN_BLK   1024
#define SCAN_NBLK  ((N_OUT + SCAN_BLK - 1) / SCAN_BLK)   // 49

// ---------------- scratch (device globals; no allocation allowed) ----------------
__device__ int   g_idx64;               // 1 if indices are int64, 0 if int32
__device__ int   g_counts[N_OUT];
__device__ int   g_offsets[N_OUT + 1];
__device__ int   g_cursor[N_OUT];
__device__ int   g_perm[E_EDGES];
__device__ int   g_blocksums[64];
__device__ int   g_blockoff[64];
__device__ float g_agg[(size_t)N_OUT * KDIM];   // 102.4 MB

// ---------------- index accessors (dtype-robust) ----------------
__device__ __forceinline__ int idx_out_of(const int* __restrict__ idx, int e, int is64) {
    return is64 ? idx[4 * e] : idx[2 * e];
}
__device__ __forceinline__ int idx_in_of(const int* __restrict__ idx, int e, int is64) {
    return is64 ? idx[4 * e + 2] : idx[2 * e + 1];
}

// ---------------- probe index dtype ----------------
__global__ void probe_kernel(const int* __restrict__ idx) {
    if (threadIdx.x == 0) {
        int nz = 0;
        for (int i = 1; i < 256; i += 2) nz |= idx[i];
        g_idx64 = (nz == 0) ? 1 : 0;
    }
}

// ---------------- zero histogram ----------------
__global__ void zero_counts_kernel() {
    int i = blockIdx.x * blockDim.x + threadIdx.x;
    if (i < N_OUT) g_counts[i] = 0;
}

// ---------------- histogram of idx_out ----------------
__global__ void hist_kernel(const int* __restrict__ idx) {
    int e = blockIdx.x * blockDim.x + threadIdx.x;
    if (e < E_EDGES) {
        int o = idx_out_of(idx, e, g_idx64);
        atomicAdd(&g_counts[o], 1);
    }
}

// ---------------- parallel scan, pass 1: per-block local exclusive scan ----------------
__global__ __launch_bounds__(SCAN_BLK) void scan_partial_kernel() {
    __shared__ int warp_sums[32];
    const int tid = threadIdx.x;
    const int b   = blockIdx.x;
    const int i   = b * SCAN_BLK + tid;
    int v = (i < N_OUT) ? g_counts[i] : 0;

    // warp inclusive scan
    int x = v;
    #pragma unroll
    for (int d = 1; d < 32; d <<= 1) {
        int y = __shfl_up_sync(0xffffffffu, x, d);
        if ((tid & 31) >= d) x += y;
    }
    if ((tid & 31) == 31) warp_sums[tid >> 5] = x;
    __syncthreads();
    if (tid < 32) {
        int s = warp_sums[tid];
        #pragma unroll
        for (int d = 1; d < 32; d <<= 1) {
            int y = __shfl_up_sync(0xffffffffu, s, d);
            if (tid >= d) s += y;
        }
        warp_sums[tid] = s;
    }
    __syncthreads();
    int warp_prefix = (tid >= 32) ? warp_sums[(tid >> 5) - 1] : 0;
    int incl = warp_prefix + x;
    if (i < N_OUT) g_offsets[i] = incl - v;        // local exclusive
    if (tid == SCAN_BLK - 1) g_blocksums[b] = incl; // block total
}

// ---------------- parallel scan, pass 2: scan the 49 block sums ----------------
__global__ __launch_bounds__(64) void scan_blocksums_kernel() {
    __shared__ int s[64];
    int tid = threadIdx.x;
    s[tid] = (tid < SCAN_NBLK) ? g_blocksums[tid] : 0;
    __syncthreads();
    // Hillis-Steele inclusive scan over 64
    #pragma unroll
    for (int d = 1; d < 64; d <<= 1) {
        int y = (tid >= d) ? s[tid - d] : 0;
        __syncthreads();
        s[tid] += y;
        __syncthreads();
    }
    g_blockoff[tid] = (tid > 0) ? s[tid - 1] : 0;   // exclusive
    if (tid == SCAN_NBLK - 1) g_offsets[N_OUT] = s[tid];
}

// ---------------- parallel scan, pass 3: add block offsets ----------------
__global__ __launch_bounds__(SCAN_BLK) void scan_add_kernel() {
    const int b = blockIdx.x;
    const int i = b * SCAN_BLK + threadIdx.x;
    if (i < N_OUT) {
        int off = g_offsets[i] + g_blockoff[b];
        g_offsets[i] = off;
        g_cursor[i]  = off;
    }
}

// ---------------- scatter edge ids into CSR slots ----------------
__global__ void fill_perm_kernel(const int* __restrict__ idx) {
    int e = blockIdx.x * blockDim.x + threadIdx.x;
    if (e < E_EDGES) {
        int o = idx_out_of(idx, e, g_idx64);
        int p = atomicAdd(&g_cursor[o], 1);
        g_perm[p] = e;
    }
}

// ---------------- pull phase: one warp per output node ----------------
__global__ __launch_bounds__(256) void pull_kernel(
    const float* __restrict__ node,
    const float* __restrict__ edgef,
    const int* __restrict__ idx)
{
    int w = blockIdx.x * 8 + (threadIdx.x >> 5);
    int lane = threadIdx.x & 31;
    int is64 = g_idx64;
    int s    = g_offsets[w];
    int send = g_offsets[w + 1];

    float accx[T_DIM], accy[T_DIM];
    #pragma unroll
    for (int t = 0; t < T_DIM; t++) { accx[t] = 0.f; accy[t] = 0.f; }

    for (int p = s; p < send; p++) {
        int e = g_perm[p];
        float wv = 0.f;
        if (lane < 8) wv = edgef[lane * E_EDGES + e];
        int nin = idx_in_of(idx, e, is64);
        float2 nv = *(const float2*)(node + (size_t)nin * 64 + lane * 2);
        #pragma unroll
        for (int t = 0; t < T_DIM; t++) {
            float wt = __shfl_sync(0xffffffffu, wv, t);
            accx[t] += wt * nv.x;
            accy[t] += wt * nv.y;
        }
    }

    size_t base = (size_t)w * KDIM + lane * 2;
    #pragma unroll
    for (int t = 0; t < T_DIM; t++) {
        *(float2*)&g_agg[base + t * 64] = make_float2(accx[t], accy[t]);
    }
}

// ---------------- GEMM: out = agg(50000x512) @ W(512x64) + bias ----------------
// Packed fma.rn.f32x2: accumulate M-row pairs. B tile stored duplicated so
// both FFMA2 operands come packed straight out of shared memory (no movs).
#define BM 128
#define BN 64
#define BK 16
#define TM 8   // rows per thread (4 packed pairs)
#define TN 4   // cols per thread

#define FMA2(acc, a, b) \
    asm("fma.rn.f32x2 %0, %1, %2, %3;" : "=l"(acc) : "l"(a), "l"(b), "l"(acc))

__global__ __launch_bounds__(256) void gemm_kernel(
    const float* __restrict__ W,      // (512, 64) row-major
    const float* __restrict__ bias,
    float* __restrict__ out)
{
    __shared__ float  As[BK][BM];           // 8 KB, A transposed
    __shared__ float2 Bsd[BK][BN];          // 8 KB, each element duplicated (b,b)

    const int tid  = threadIdx.x;
    const int row0 = blockIdx.x * BM;
    const int tx   = tid % 16;   // cols tx*4 .. tx*4+3
    const int ty   = tid / 16;   // rows ty*8 .. ty*8+7

    unsigned long long acc2[TM / 2][TN];   // [row-pair][col]
    #pragma unroll
    for (int i = 0; i < TM / 2; i++)
        #pragma unroll
        for (int j = 0; j < TN; j++) acc2[i][j] = 0ull;

    for (int k0 = 0; k0 < KDIM; k0 += BK) {
        // A tile: 128x16 -> transposed into As[k][m]. 512 float4, 2/thread.
        #pragma unroll
        for (int i = 0; i < 2; i++) {
            int idx4 = tid * 2 + i;
            int r   = idx4 >> 2;
            int c4  = idx4 & 3;
            int gr  = row0 + r;
            float4 v = make_float4(0.f, 0.f, 0.f, 0.f);
            if (gr < N_OUT)
                v = *(const float4*)&g_agg[(size_t)gr * KDIM + k0 + c4 * 4];
            As[c4 * 4 + 0][r] = v.x;
            As[c4 * 4 + 1][r] = v.y;
            As[c4 * 4 + 2][r] = v.z;
            As[c4 * 4 + 3][r] = v.w;
        }
        // B tile: 16x64, stored duplicated. 1 float4 load, 2 float4 stores.
        {
            int kr = tid >> 4;
            int c4 = tid & 15;
            float4 v = *(const float4*)&W[(size_t)(k0 + kr) * 64 + c4 * 4];
            float4* p = (float4*)&Bsd[kr][c4 * 4];
            p[0] = make_float4(v.x, v.x, v.y, v.y);
            p[1] = make_float4(v.z, v.z, v.w, v.w);
        }
        __syncthreads();

        #pragma unroll
        for (int kk = 0; kk < BK; kk++) {
            // 4 packed row-pairs of A (adjacent floats -> natural 64-bit pairs)
            ulonglong2 aq0 = *(const ulonglong2*)&As[kk][ty * TM];
            ulonglong2 aq1 = *(const ulonglong2*)&As[kk][ty * TM + 4];
            // 4 duplicated B scalars (pre-packed in shared)
            ulonglong2 bq0 = *(const ulonglong2*)&Bsd[kk][tx * TN];
            ulonglong2 bq1 = *(const ulonglong2*)&Bsd[kk][tx * TN + 2];
            unsigned long long a2[4] = { aq0.x, aq0.y, aq1.x, aq1.y };
            unsigned long long b2[4] = { bq0.x, bq0.y, bq1.x, bq1.y };
            #pragma unroll
            for (int i = 0; i < 4; i++)
                #pragma unroll
                for (int j = 0; j < 4; j++)
                    FMA2(acc2[i][j], a2[i], b2[j]);
        }
        __syncthreads();
    }

    float4 bv = *(const float4*)&bias[tx * TN];
    float bb[4] = { bv.x, bv.y, bv.z, bv.w };
    #pragma unroll
    for (int i = 0; i < TM / 2; i++) {
        int r0 = row0 + ty * TM + 2 * i;
        float lo[4], hi[4];
        #pragma unroll
        for (int j = 0; j < 4; j++) {
            unsigned int l, h;
            asm("mov.b64 {%0, %1}, %2;" : "=r"(l), "=r"(h) : "l"(acc2[i][j]));
            lo[j] = __uint_as_float(l) + bb[j];
            hi[j] = __uint_as_float(h) + bb[j];
        }
        if (r0 < N_OUT)
            *(float4*)&out[(size_t)r0 * F_DIM + tx * TN] = make_float4(lo[0], lo[1], lo[2], lo[3]);
        if (r0 + 1 < N_OUT)
            *(float4*)&out[(size_t)(r0 + 1) * F_DIM + tx * TN] = make_float4(hi[0], hi[1], hi[2], hi[3]);
    }
}

// ---------------- launch ----------------
extern "C" void kernel_launch(void* const* d_in, const int* in_sizes, int n_in,
                              void* d_out, int out_size)
{
    const float* node  = nullptr;
    const float* edgef = nullptr;
    const int*   idx   = nullptr;
    const float* W     = nullptr;
    const float* bias  = nullptr;

    for (int i = 0; i < n_in; i++) {
        switch (in_sizes[i]) {
            case N_IN * C_DIM:          node  = (const float*)d_in[i]; break;
            case T_DIM * E_EDGES:       edgef = (const float*)d_in[i]; break;
            case E_EDGES * 2:           idx   = (const int*)d_in[i];   break;
            case T_DIM * C_DIM * F_DIM: W     = (const float*)d_in[i]; break;
            case F_DIM:                 bias  = (const float*)d_in[i]; break;
            default: break;
        }
    }
    float* out = (float*)d_out;

    probe_kernel<<<1, 32>>>(idx);
    zero_counts_kernel<<<(N_OUT + 255) / 256, 256>>>();
    hist_kernel<<<(E_EDGES + 255) / 256, 256>>>(idx);
    scan_partial_kernel<<<SCAN_NBLK, SCAN_BLK>>>();
    scan_blocksums_kernel<<<1, 64>>>();
    scan_add_kernel<<<SCAN_NBLK, SCAN_BLK>>>();
    fill_perm_kernel<<<(E_EDGES + 255) / 256, 256>>>(idx);
    pull_kernel<<<N_OUT / 8, 256>>>(node, edgef, idx);
    gemm_kernel<<<(N_OUT + BM - 1) / BM, 256>>>(W, bias, out);
}

// round 12
// speedup vs baseline: 1.2048x; 1.2048x over previous
#include <cuda_runtime.h>
#include <cstdint>

#define N_IN    50000
#define C_DIM   64
#define T_DIM   8
#define E_EDGES 800000
#define N_OUT   50000
#define F_DIM   64
#define KDIM    512   // T*C

#define SCAN_BLK   1024
#define SCAN_NBLK  ((N_OUT + SCAN_BLK - 1) / SCAN_BLK)   // 49

// ---------------- scratch (device globals; no allocation allowed) ----------------
__device__ int   g_idx64;               // 1 if indices are int64, 0 if int32
__device__ int   g_counts[N_OUT];
__device__ int   g_offsets[N_OUT + 1];
__device__ int   g_cursor[N_OUT];
__device__ int   g_perm[E_EDGES];
__device__ int   g_blocksums[64];
__device__ int   g_blockoff[64];
__device__ float g_edgeT[(size_t)E_EDGES * T_DIM];   // 25.6 MB, edge-major [e][t]
__device__ float g_agg[(size_t)N_OUT * KDIM];        // 102.4 MB

// ---------------- index accessors (dtype-robust) ----------------
__device__ __forceinline__ int idx_out_of(const int* __restrict__ idx, int e, int is64) {
    // int32 layout: [out0,in0,out1,in1,...]; int64 little-endian: [out0,0,in0,0,...]
    return is64 ? idx[4 * e] : idx[2 * e];
}
__device__ __forceinline__ int idx_in_of(const int* __restrict__ idx, int e, int is64) {
    return is64 ? idx[4 * e + 2] : idx[2 * e + 1];
}

// ---------------- probe index dtype ----------------
__global__ void probe_kernel(const int* __restrict__ idx) {
    if (threadIdx.x == 0) {
        int nz = 0;
        for (int i = 1; i < 256; i += 2) nz |= idx[i];
        g_idx64 = (nz == 0) ? 1 : 0;
    }
}

// ---------------- zero histogram ----------------
__global__ void zero_counts_kernel() {
    int i = blockIdx.x * blockDim.x + threadIdx.x;
    if (i < N_OUT) g_counts[i] = 0;
}

// ---------------- histogram of idx_out ----------------
__global__ void hist_kernel(const int* __restrict__ idx) {
    int e = blockIdx.x * blockDim.x + threadIdx.x;
    if (e < E_EDGES) atomicAdd(&g_counts[idx_out_of(idx, e, g_idx64)], 1);
}

// ---------------- parallel scan, pass 1 ----------------
__global__ __launch_bounds__(SCAN_BLK) void scan_partial_kernel() {
    __shared__ int warp_sums[32];
    const int tid = threadIdx.x;
    const int b   = blockIdx.x;
    const int i   = b * SCAN_BLK + tid;
    int v = (i < N_OUT) ? g_counts[i] : 0;
    int x = v;
    #pragma unroll
    for (int d = 1; d < 32; d <<= 1) {
        int y = __shfl_up_sync(0xffffffffu, x, d);
        if ((tid & 31) >= d) x += y;
    }
    if ((tid & 31) == 31) warp_sums[tid >> 5] = x;
    __syncthreads();
    if (tid < 32) {
        int s = warp_sums[tid];
        #pragma unroll
        for (int d = 1; d < 32; d <<= 1) {
            int y = __shfl_up_sync(0xffffffffu, s, d);
            if (tid >= d) s += y;
        }
        warp_sums[tid] = s;
    }
    __syncthreads();
    int warp_prefix = (tid >= 32) ? warp_sums[(tid >> 5) - 1] : 0;
    int incl = warp_prefix + x;
    if (i < N_OUT) g_offsets[i] = incl - v;
    if (tid == SCAN_BLK - 1) g_blocksums[b] = incl;
}

// ---------------- parallel scan, pass 2 ----------------
__global__ __launch_bounds__(64) void scan_blocksums_kernel() {
    __shared__ int s[64];
    int tid = threadIdx.x;
    s[tid] = (tid < SCAN_NBLK) ? g_blocksums[tid] : 0;
    __syncthreads();
    #pragma unroll
    for (int d = 1; d < 64; d <<= 1) {
        int y = (tid >= d) ? s[tid - d] : 0;
        __syncthreads();
        s[tid] += y;
        __syncthreads();
    }
    g_blockoff[tid] = (tid > 0) ? s[tid - 1] : 0;
    if (tid == SCAN_NBLK - 1) g_offsets[N_OUT] = s[tid];
}

// ---------------- parallel scan, pass 3 ----------------
__global__ __launch_bounds__(SCAN_BLK) void scan_add_kernel() {
    const int i = blockIdx.x * SCAN_BLK + threadIdx.x;
    if (i < N_OUT) {
        int off = g_offsets[i] + g_blockoff[blockIdx.x];
        g_offsets[i] = off;
        g_cursor[i]  = off;
    }
}

// ---------------- scatter edge ids into CSR slots ----------------
__global__ void fill_perm_kernel(const int* __restrict__ idx) {
    int e = blockIdx.x * blockDim.x + threadIdx.x;
    if (e < E_EDGES) {
        int p = atomicAdd(&g_cursor[idx_out_of(idx, e, g_idx64)], 1);
        g_perm[p] = e;
    }
}

// ---------------- transpose edge features to edge-major [E][8] ----------------
// Reads coalesced per-t; writes two float4 per edge (warp covers 1KB contiguous).
__global__ void transpose_edgef_kernel(const float* __restrict__ edgef) {
    int e = blockIdx.x * blockDim.x + threadIdx.x;
    if (e < E_EDGES) {
        float v[T_DIM];
        #pragma unroll
        for (int t = 0; t < T_DIM; t++)
            v[t] = edgef[(size_t)t * E_EDGES + e];
        float4* dst = (float4*)&g_edgeT[(size_t)e * T_DIM];
        dst[0] = make_float4(v[0], v[1], v[2], v[3]);
        dst[1] = make_float4(v[4], v[5], v[6], v[7]);
    }
}

// ---------------- pull phase: one warp per output node, 2-way edge MLP -------
__global__ __launch_bounds__(256) void pull_kernel(
    const float* __restrict__ node,
    const int* __restrict__ idx)
{
    int w = blockIdx.x * 8 + (threadIdx.x >> 5);
    int lane = threadIdx.x & 31;
    int is64 = g_idx64;
    int s    = g_offsets[w];
    int send = g_offsets[w + 1];

    float accx[T_DIM], accy[T_DIM];
    #pragma unroll
    for (int t = 0; t < T_DIM; t++) { accx[t] = 0.f; accy[t] = 0.f; }

    int p = s;
    for (; p + 2 <= send; p += 2) {
        int e0 = g_perm[p];
        int e1 = g_perm[p + 1];
        float wv0 = 0.f, wv1 = 0.f;
        if (lane < 8) {
            wv0 = g_edgeT[(size_t)e0 * T_DIM + lane];
            wv1 = g_edgeT[(size_t)e1 * T_DIM + lane];
        }
        int nin0 = idx_in_of(idx, e0, is64);
        int nin1 = idx_in_of(idx, e1, is64);
        float2 nv0 = *(const float2*)(node + (size_t)nin0 * 64 + lane * 2);
        float2 nv1 = *(const float2*)(node + (size_t)nin1 * 64 + lane * 2);
        #pragma unroll
        for (int t = 0; t < T_DIM; t++) {
            float wt0 = __shfl_sync(0xffffffffu, wv0, t);
            float wt1 = __shfl_sync(0xffffffffu, wv1, t);
            accx[t] += wt0 * nv0.x + wt1 * nv1.x;
            accy[t] += wt0 * nv0.y + wt1 * nv1.y;
        }
    }
    if (p < send) {
        int e = g_perm[p];
        float wv = 0.f;
        if (lane < 8) wv = g_edgeT[(size_t)e * T_DIM + lane];
        int nin = idx_in_of(idx, e, is64);
        float2 nv = *(const float2*)(node + (size_t)nin * 64 + lane * 2);
        #pragma unroll
        for (int t = 0; t < T_DIM; t++) {
            float wt = __shfl_sync(0xffffffffu, wv, t);
            accx[t] += wt * nv.x;
            accy[t] += wt * nv.y;
        }
    }

    size_t base = (size_t)w * KDIM + lane * 2;
    #pragma unroll
    for (int t = 0; t < T_DIM; t++)
        *(float2*)&g_agg[base + t * 64] = make_float2(accx[t], accy[t]);
}

// ---------------- GEMM: out = agg(50000x512) @ W(512x64) + bias --------------
// R3-proven scalar fp32 register-blocked SGEMM (8x4 per thread).
#define BM 128
#define BN 64
#define BK 16
#define TM 8
#define TN 4

__global__ __launch_bounds__(256) void gemm_kernel(
    const float* __restrict__ W,      // (T*C, F) row-major
    const float* __restrict__ bias,
    float* __restrict__ out)
{
    __shared__ float As[BK][BM];
    __shared__ float Bs[BK][BN];

    const int tid  = threadIdx.x;
    const int row0 = blockIdx.x * BM;
    const int tx   = tid % 16;   // cols tx*4 .. tx*4+3
    const int ty   = tid / 16;   // rows ty*8 .. ty*8+7

    float acc[TM][TN];
    #pragma unroll
    for (int i = 0; i < TM; i++)
        #pragma unroll
        for (int j = 0; j < TN; j++) acc[i][j] = 0.f;

    for (int k0 = 0; k0 < KDIM; k0 += BK) {
        #pragma unroll
        for (int i = 0; i < 2; i++) {
            int idx4 = tid * 2 + i;
            int r   = idx4 >> 2;
            int c4  = idx4 & 3;
            int gr  = row0 + r;
            float4 v = make_float4(0.f, 0.f, 0.f, 0.f);
            if (gr < N_OUT)
                v = *(const float4*)&g_agg[(size_t)gr * KDIM + k0 + c4 * 4];
            As[c4 * 4 + 0][r] = v.x;
            As[c4 * 4 + 1][r] = v.y;
            As[c4 * 4 + 2][r] = v.z;
            As[c4 * 4 + 3][r] = v.w;
        }
        {
            int kr = tid >> 4;
            int c4 = tid & 15;
            float4 v = *(const float4*)&W[(size_t)(k0 + kr) * 64 + c4 * 4];
            *(float4*)&Bs[kr][c4 * 4] = v;
        }
        __syncthreads();

        #pragma unroll
        for (int kk = 0; kk < BK; kk++) {
            float a[TM], b[TN];
            #pragma unroll
            for (int i = 0; i < TM; i++) a[i] = As[kk][ty * TM + i];
            #pragma unroll
            for (int j = 0; j < TN; j++) b[j] = Bs[kk][tx * TN + j];
            #pragma unroll
            for (int i = 0; i < TM; i++)
                #pragma unroll
                for (int j = 0; j < TN; j++)
                    acc[i][j] += a[i] * b[j];
        }
        __syncthreads();
    }

    float4 bv = *(const float4*)&bias[tx * TN];
    #pragma unroll
    for (int i = 0; i < TM; i++) {
        int gr = row0 + ty * TM + i;
        if (gr < N_OUT) {
            float4 o;
            o.x = acc[i][0] + bv.x;
            o.y = acc[i][1] + bv.y;
            o.z = acc[i][2] + bv.z;
            o.w = acc[i][3] + bv.w;
            *(float4*)&out[(size_t)gr * F_DIM + tx * TN] = o;
        }
    }
}

// ---------------- launch ----------------
extern "C" void kernel_launch(void* const* d_in, const int* in_sizes, int n_in,
                              void* d_out, int out_size)
{
    const float* node  = nullptr;
    const float* edgef = nullptr;
    const int*   idx   = nullptr;
    const float* W     = nullptr;
    const float* bias  = nullptr;

    for (int i = 0; i < n_in; i++) {
        switch (in_sizes[i]) {
            case N_IN * C_DIM:          node  = (const float*)d_in[i]; break;
            case T_DIM * E_EDGES:       edgef = (const float*)d_in[i]; break;
            case E_EDGES * 2:           idx   = (const int*)d_in[i];   break;
            case T_DIM * C_DIM * F_DIM: W     = (const float*)d_in[i]; break;
            case F_DIM:                 bias  = (const float*)d_in[i]; break;
            default: break;
        }
    }
    float* out = (float*)d_out;

    probe_kernel<<<1, 32>>>(idx);
    zero_counts_kernel<<<(N_OUT + 255) / 256, 256>>>();
    hist_kernel<<<(E_EDGES + 255) / 256, 256>>>(idx);
    scan_partial_kernel<<<SCAN_NBLK, SCAN_BLK>>>();
    scan_blocksums_kernel<<<1, 64>>>();
    scan_add_kernel<<<SCAN_NBLK, SCAN_BLK>>>();
    fill_perm_kernel<<<(E_EDGES + 255) / 256, 256>>>(idx);
    transpose_edgef_kernel<<<(E_EDGES + 255) / 256, 256>>>(edgef);
    pull_kernel<<<N_OUT / 8, 256>>>(node, idx);
    gemm_kernel<<<(N_OUT + BM - 1) / BM, 256>>>(W, bias, out);
}

// round 13
// speedup vs baseline: 1.2852x; 1.0668x over previous
#include <cuda_runtime.h>
#include <cstdint>

#define N_IN    50000
#define C_DIM   64
#define T_DIM   8
#define E_EDGES 800000
#define N_OUT   50000
#define F_DIM   64
#define KDIM    512   // T*C

#define SCAN_BLK   1024
#define SCAN_NBLK  ((N_OUT + SCAN_BLK - 1) / SCAN_BLK)   // 49

// ---------------- scratch (device globals; no allocation allowed) ----------------
__device__ int   g_idx64;               // 1 if indices are int64, 0 if int32
__device__ int   g_counts[N_OUT];
__device__ int   g_offsets[N_OUT + 1];
__device__ int   g_cursor[N_OUT];
__device__ int   g_perm[E_EDGES];
__device__ int   g_blocksums[64];
__device__ int   g_blockoff[64];
__device__ float g_edgeT[(size_t)E_EDGES * T_DIM];   // 25.6 MB, edge-major [e][t]
__device__ float g_agg[(size_t)N_OUT * KDIM];        // 102.4 MB

// ---------------- index accessors (dtype-robust) ----------------
__device__ __forceinline__ int idx_out_of(const int* __restrict__ idx, int e, int is64) {
    return is64 ? idx[4 * e] : idx[2 * e];
}
__device__ __forceinline__ int idx_in_of(const int* __restrict__ idx, int e, int is64) {
    return is64 ? idx[4 * e + 2] : idx[2 * e + 1];
}

// ---------------- probe index dtype ----------------
__global__ void probe_kernel(const int* __restrict__ idx) {
    if (threadIdx.x == 0) {
        int nz = 0;
        for (int i = 1; i < 256; i += 2) nz |= idx[i];
        g_idx64 = (nz == 0) ? 1 : 0;
    }
}

// ---------------- zero histogram ----------------
__global__ void zero_counts_kernel() {
    int i = blockIdx.x * blockDim.x + threadIdx.x;
    if (i < N_OUT) g_counts[i] = 0;
}

// ---------------- fused: histogram + transpose edge features to [E][8] -------
__global__ void hist_transpose_kernel(const float* __restrict__ edgef,
                                      const int* __restrict__ idx) {
    int e = blockIdx.x * blockDim.x + threadIdx.x;
    if (e < E_EDGES) {
        atomicAdd(&g_counts[idx_out_of(idx, e, g_idx64)], 1);
        float v[T_DIM];
        #pragma unroll
        for (int t = 0; t < T_DIM; t++)
            v[t] = edgef[(size_t)t * E_EDGES + e];
        float4* dst = (float4*)&g_edgeT[(size_t)e * T_DIM];
        dst[0] = make_float4(v[0], v[1], v[2], v[3]);
        dst[1] = make_float4(v[4], v[5], v[6], v[7]);
    }
}

// ---------------- parallel scan, pass 1 ----------------
__global__ __launch_bounds__(SCAN_BLK) void scan_partial_kernel() {
    __shared__ int warp_sums[32];
    const int tid = threadIdx.x;
    const int b   = blockIdx.x;
    const int i   = b * SCAN_BLK + tid;
    int v = (i < N_OUT) ? g_counts[i] : 0;
    int x = v;
    #pragma unroll
    for (int d = 1; d < 32; d <<= 1) {
        int y = __shfl_up_sync(0xffffffffu, x, d);
        if ((tid & 31) >= d) x += y;
    }
    if ((tid & 31) == 31) warp_sums[tid >> 5] = x;
    __syncthreads();
    if (tid < 32) {
        int s = warp_sums[tid];
        #pragma unroll
        for (int d = 1; d < 32; d <<= 1) {
            int y = __shfl_up_sync(0xffffffffu, s, d);
            if (tid >= d) s += y;
        }
        warp_sums[tid] = s;
    }
    __syncthreads();
    int warp_prefix = (tid >= 32) ? warp_sums[(tid >> 5) - 1] : 0;
    int incl = warp_prefix + x;
    if (i < N_OUT) g_offsets[i] = incl - v;
    if (tid == SCAN_BLK - 1) g_blocksums[b] = incl;
}

// ---------------- parallel scan, pass 2 ----------------
__global__ __launch_bounds__(64) void scan_blocksums_kernel() {
    __shared__ int s[64];
    int tid = threadIdx.x;
    s[tid] = (tid < SCAN_NBLK) ? g_blocksums[tid] : 0;
    __syncthreads();
    #pragma unroll
    for (int d = 1; d < 64; d <<= 1) {
        int y = (tid >= d) ? s[tid - d] : 0;
        __syncthreads();
        s[tid] += y;
        __syncthreads();
    }
    g_blockoff[tid] = (tid > 0) ? s[tid - 1] : 0;
    if (tid == SCAN_NBLK - 1) g_offsets[N_OUT] = s[tid];
}

// ---------------- parallel scan, pass 3 ----------------
__global__ __launch_bounds__(SCAN_BLK) void scan_add_kernel() {
    const int i = blockIdx.x * SCAN_BLK + threadIdx.x;
    if (i < N_OUT) {
        int off = g_offsets[i] + g_blockoff[blockIdx.x];
        g_offsets[i] = off;
        g_cursor[i]  = off;
    }
}

// ---------------- scatter edge ids into CSR slots ----------------
__global__ void fill_perm_kernel(const int* __restrict__ idx) {
    int e = blockIdx.x * blockDim.x + threadIdx.x;
    if (e < E_EDGES) {
        int p = atomicAdd(&g_cursor[idx_out_of(idx, e, g_idx64)], 1);
        g_perm[p] = e;
    }
}

// ---------------- pull phase: one warp per output node, 2-way edge MLP -------
__global__ __launch_bounds__(256) void pull_kernel(
    const float* __restrict__ node,
    const int* __restrict__ idx)
{
    int w = blockIdx.x * 8 + (threadIdx.x >> 5);
    int lane = threadIdx.x & 31;
    int is64 = g_idx64;
    int s    = g_offsets[w];
    int send = g_offsets[w + 1];

    float accx[T_DIM], accy[T_DIM];
    #pragma unroll
    for (int t = 0; t < T_DIM; t++) { accx[t] = 0.f; accy[t] = 0.f; }

    int p = s;
    for (; p + 2 <= send; p += 2) {
        int e0 = g_perm[p];
        int e1 = g_perm[p + 1];
        float wv0 = 0.f, wv1 = 0.f;
        if (lane < 8) {
            wv0 = g_edgeT[(size_t)e0 * T_DIM + lane];
            wv1 = g_edgeT[(size_t)e1 * T_DIM + lane];
        }
        int nin0 = idx_in_of(idx, e0, is64);
        int nin1 = idx_in_of(idx, e1, is64);
        float2 nv0 = *(const float2*)(node + (size_t)nin0 * 64 + lane * 2);
        float2 nv1 = *(const float2*)(node + (size_t)nin1 * 64 + lane * 2);
        #pragma unroll
        for (int t = 0; t < T_DIM; t++) {
            float wt0 = __shfl_sync(0xffffffffu, wv0, t);
            float wt1 = __shfl_sync(0xffffffffu, wv1, t);
            accx[t] += wt0 * nv0.x + wt1 * nv1.x;
            accy[t] += wt0 * nv0.y + wt1 * nv1.y;
        }
    }
    if (p < send) {
        int e = g_perm[p];
        float wv = 0.f;
        if (lane < 8) wv = g_edgeT[(size_t)e * T_DIM + lane];
        int nin = idx_in_of(idx, e, is64);
        float2 nv = *(const float2*)(node + (size_t)nin * 64 + lane * 2);
        #pragma unroll
        for (int t = 0; t < T_DIM; t++) {
            float wt = __shfl_sync(0xffffffffu, wv, t);
            accx[t] += wt * nv.x;
            accy[t] += wt * nv.y;
        }
    }

    size_t base = (size_t)w * KDIM + lane * 2;
    #pragma unroll
    for (int t = 0; t < T_DIM; t++)
        *(float2*)&g_agg[base + t * 64] = make_float2(accx[t], accy[t]);
}

// ---------------- GEMM: out = agg(50000x512) @ W(512x64) + bias --------------
// Same tiling/layout/loads as the proven R3 kernel; only the inner product is
// switched to packed fma.rn.f32x2 with in-register B duplication.
#define BM 128
#define BN 64
#define BK 16
#define TM 8
#define TN 4

__global__ __launch_bounds__(256) void gemm_kernel(
    const float* __restrict__ W,      // (T*C, F) row-major
    const float* __restrict__ bias,
    float* __restrict__ out)
{
    __shared__ float As[BK][BM];
    __shared__ float Bs[BK][BN];

    const int tid  = threadIdx.x;
    const int row0 = blockIdx.x * BM;
    const int tx   = tid % 16;   // cols tx*4 .. tx*4+3
    const int ty   = tid / 16;   // rows ty*8 .. ty*8+7

    // acc2[i][j]: packed pair (row 2i, row 2i+1) x col j
    unsigned long long acc2[TM / 2][TN];
    #pragma unroll
    for (int i = 0; i < TM / 2; i++)
        #pragma unroll
        for (int j = 0; j < TN; j++) acc2[i][j] = 0ull;

    for (int k0 = 0; k0 < KDIM; k0 += BK) {
        #pragma unroll
        for (int i = 0; i < 2; i++) {
            int idx4 = tid * 2 + i;
            int r   = idx4 >> 2;
            int c4  = idx4 & 3;
            int gr  = row0 + r;
            float4 v = make_float4(0.f, 0.f, 0.f, 0.f);
            if (gr < N_OUT)
                v = *(const float4*)&g_agg[(size_t)gr * KDIM + k0 + c4 * 4];
            As[c4 * 4 + 0][r] = v.x;
            As[c4 * 4 + 1][r] = v.y;
            As[c4 * 4 + 2][r] = v.z;
            As[c4 * 4 + 3][r] = v.w;
        }
        {
            int kr = tid >> 4;
            int c4 = tid & 15;
            float4 v = *(const float4*)&W[(size_t)(k0 + kr) * 64 + c4 * 4];
            *(float4*)&Bs[kr][c4 * 4] = v;
        }
        __syncthreads();

        #pragma unroll
        for (int kk = 0; kk < BK; kk++) {
            // A row-pairs: same addresses as scalar version (2 x LDS.128)
            ulonglong2 aq0 = *(const ulonglong2*)&As[kk][ty * TM];
            ulonglong2 aq1 = *(const ulonglong2*)&As[kk][ty * TM + 4];
            unsigned long long a2[4] = { aq0.x, aq0.y, aq1.x, aq1.y };
            // B scalars: same load as scalar version (1 x LDS.128), dup in regs
            float4 bq = *(const float4*)&Bs[kk][tx * TN];
            unsigned long long b2[4];
            asm("mov.b64 %0, {%1, %1};" : "=l"(b2[0]) : "r"(__float_as_uint(bq.x)));
            asm("mov.b64 %0, {%1, %1};" : "=l"(b2[1]) : "r"(__float_as_uint(bq.y)));
            asm("mov.b64 %0, {%1, %1};" : "=l"(b2[2]) : "r"(__float_as_uint(bq.z)));
            asm("mov.b64 %0, {%1, %1};" : "=l"(b2[3]) : "r"(__float_as_uint(bq.w)));
            #pragma unroll
            for (int i = 0; i < 4; i++)
                #pragma unroll
                for (int j = 0; j < 4; j++)
                    asm("fma.rn.f32x2 %0, %1, %2, %0;"
                        : "+l"(acc2[i][j]) : "l"(a2[i]), "l"(b2[j]));
        }
        __syncthreads();
    }

    float4 bv = *(const float4*)&bias[tx * TN];
    float bb[4] = { bv.x, bv.y, bv.z, bv.w };
    #pragma unroll
    for (int i = 0; i < TM / 2; i++) {
        int r0 = row0 + ty * TM + 2 * i;
        float lo[4], hi[4];
        #pragma unroll
        for (int j = 0; j < 4; j++) {
            unsigned int l, h;
            asm("mov.b64 {%0, %1}, %2;" : "=r"(l), "=r"(h) : "l"(acc2[i][j]));
            lo[j] = __uint_as_float(l) + bb[j];
            hi[j] = __uint_as_float(h) + bb[j];
        }
        if (r0 < N_OUT)
            *(float4*)&out[(size_t)r0 * F_DIM + tx * TN] = make_float4(lo[0], lo[1], lo[2], lo[3]);
        if (r0 + 1 < N_OUT)
            *(float4*)&out[(size_t)(r0 + 1) * F_DIM + tx * TN] = make_float4(hi[0], hi[1], hi[2], hi[3]);
    }
}

// ---------------- launch ----------------
extern "C" void kernel_launch(void* const* d_in, const int* in_sizes, int n_in,
                              void* d_out, int out_size)
{
    const float* node  = nullptr;
    const float* edgef = nullptr;
    const int*   idx   = nullptr;
    const float* W     = nullptr;
    const float* bias  = nullptr;

    for (int i = 0; i < n_in; i++) {
        switch (in_sizes[i]) {
            case N_IN * C_DIM:          node  = (const float*)d_in[i]; break;
            case T_DIM * E_EDGES:       edgef = (const float*)d_in[i]; break;
            case E_EDGES * 2:           idx   = (const int*)d_in[i];   break;
            case T_DIM * C_DIM * F_DIM: W     = (const float*)d_in[i]; break;
            case F_DIM:                 bias  = (const float*)d_in[i]; break;
            default: break;
        }
    }
    float* out = (float*)d_out;

    probe_kernel<<<1, 32>>>(idx);
    zero_counts_kernel<<<(N_OUT + 255) / 256, 256>>>();
    hist_transpose_kernel<<<(E_EDGES + 255) / 256, 256>>>(edgef, idx);
    scan_partial_kernel<<<SCAN_NBLK, SCAN_BLK>>>();
    scan_blocksums_kernel<<<1, 64>>>();
    scan_add_kernel<<<SCAN_NBLK, SCAN_BLK>>>();
    fill_perm_kernel<<<(E_EDGES + 255) / 256, 256>>>(idx);
    pull_kernel<<<N_OUT / 8, 256>>>(node, idx);
    gemm_kernel<<<(N_OUT + BM - 1) / BM, 256>>>(W, bias, out);
}

// round 16
// speedup vs baseline: 1.3186x; 1.0259x over previous
#include <cuda_runtime.h>
#include <cstdint>

#define N_IN    50000
#define C_DIM   64
#define T_DIM   8
#define E_EDGES 800000
#define N_OUT   50000
#define F_DIM   64
#define KDIM    512   // T*C

#define SCAN_BLK   1024
#define SCAN_NBLK  ((N_OUT + SCAN_BLK - 1) / SCAN_BLK)   // 49

// ---------------- scratch (device globals; no allocation allowed) ----------------
__device__ int   g_idx64;               // 1 if indices are int64, 0 if int32
__device__ int   g_counts[N_OUT];
__device__ int   g_offsets[N_OUT + 1];
__device__ int   g_cursor[N_OUT];
__device__ int   g_perm[E_EDGES];
__device__ int   g_blocksums[64];
__device__ int   g_blockoff[64];
__device__ float g_edgeT[(size_t)E_EDGES * T_DIM];   // 25.6 MB, edge-major [e][t]
__device__ float g_agg[(size_t)N_OUT * KDIM];        // 102.4 MB

// ---------------- index accessors (dtype-robust) ----------------
__device__ __forceinline__ int idx_out_of(const int* __restrict__ idx, int e, int is64) {
    return is64 ? idx[4 * e] : idx[2 * e];
}
__device__ __forceinline__ int idx_in_of(const int* __restrict__ idx, int e, int is64) {
    return is64 ? idx[4 * e + 2] : idx[2 * e + 1];
}

// ---------------- probe index dtype ----------------
__global__ void probe_kernel(const int* __restrict__ idx) {
    if (threadIdx.x == 0) {
        int nz = 0;
        for (int i = 1; i < 256; i += 2) nz |= idx[i];
        g_idx64 = (nz == 0) ? 1 : 0;
    }
}

// ---------------- zero histogram ----------------
__global__ void zero_counts_kernel() {
    int i = blockIdx.x * blockDim.x + threadIdx.x;
    if (i < N_OUT) g_counts[i] = 0;
}

// ---------------- fused: histogram + transpose edge features to [E][8] -------
__global__ void hist_transpose_kernel(const float* __restrict__ edgef,
                                      const int* __restrict__ idx) {
    int e = blockIdx.x * blockDim.x + threadIdx.x;
    if (e < E_EDGES) {
        atomicAdd(&g_counts[idx_out_of(idx, e, g_idx64)], 1);
        float v[T_DIM];
        #pragma unroll
        for (int t = 0; t < T_DIM; t++)
            v[t] = edgef[(size_t)t * E_EDGES + e];
        float4* dst = (float4*)&g_edgeT[(size_t)e * T_DIM];
        dst[0] = make_float4(v[0], v[1], v[2], v[3]);
        dst[1] = make_float4(v[4], v[5], v[6], v[7]);
    }
}

// ---------------- parallel scan, pass 1 ----------------
__global__ __launch_bounds__(SCAN_BLK) void scan_partial_kernel() {
    __shared__ int warp_sums[32];
    const int tid = threadIdx.x;
    const int b   = blockIdx.x;
    const int i   = b * SCAN_BLK + tid;
    int v = (i < N_OUT) ? g_counts[i] : 0;
    int x = v;
    #pragma unroll
    for (int d = 1; d < 32; d <<= 1) {
        int y = __shfl_up_sync(0xffffffffu, x, d);
        if ((tid & 31) >= d) x += y;
    }
    if ((tid & 31) == 31) warp_sums[tid >> 5] = x;
    __syncthreads();
    if (tid < 32) {
        int s = warp_sums[tid];
        #pragma unroll
        for (int d = 1; d < 32; d <<= 1) {
            int y = __shfl_up_sync(0xffffffffu, s, d);
            if (tid >= d) s += y;
        }
        warp_sums[tid] = s;
    }
    __syncthreads();
    int warp_prefix = (tid >= 32) ? warp_sums[(tid >> 5) - 1] : 0;
    int incl = warp_prefix + x;
    if (i < N_OUT) g_offsets[i] = incl - v;
    if (tid == SCAN_BLK - 1) g_blocksums[b] = incl;
}

// ---------------- parallel scan, pass 2 ----------------
__global__ __launch_bounds__(64) void scan_blocksums_kernel() {
    __shared__ int s[64];
    int tid = threadIdx.x;
    s[tid] = (tid < SCAN_NBLK) ? g_blocksums[tid] : 0;
    __syncthreads();
    #pragma unroll
    for (int d = 1; d < 64; d <<= 1) {
        int y = (tid >= d) ? s[tid - d] : 0;
        __syncthreads();
        s[tid] += y;
        __syncthreads();
    }
    g_blockoff[tid] = (tid > 0) ? s[tid - 1] : 0;
    if (tid == SCAN_NBLK - 1) g_offsets[N_OUT] = s[tid];
}

// ---------------- parallel scan, pass 3 ----------------
__global__ __launch_bounds__(SCAN_BLK) void scan_add_kernel() {
    const int i = blockIdx.x * SCAN_BLK + threadIdx.x;
    if (i < N_OUT) {
        int off = g_offsets[i] + g_blockoff[blockIdx.x];
        g_offsets[i] = off;
        g_cursor[i]  = off;
    }
}

// ---------------- scatter edge ids into CSR slots ----------------
__global__ void fill_perm_kernel(const int* __restrict__ idx) {
    int e = blockIdx.x * blockDim.x + threadIdx.x;
    if (e < E_EDGES) {
        int p = atomicAdd(&g_cursor[idx_out_of(idx, e, g_idx64)], 1);
        g_perm[p] = e;
    }
}

// ---------------- pull phase: one warp per node; broadcast weight loads ------
__global__ __launch_bounds__(256) void pull_kernel(
    const float* __restrict__ node,
    const int* __restrict__ idx)
{
    int w = blockIdx.x * 8 + (threadIdx.x >> 5);
    int lane = threadIdx.x & 31;
    int is64 = g_idx64;
    int s    = g_offsets[w];
    int send = g_offsets[w + 1];

    float accx[T_DIM], accy[T_DIM];
    #pragma unroll
    for (int t = 0; t < T_DIM; t++) { accx[t] = 0.f; accy[t] = 0.f; }

    int p = s;
    for (; p + 2 <= send; p += 2) {
        int e0 = g_perm[p];
        int e1 = g_perm[p + 1];
        // all lanes load the same 32B — warp-broadcast, 1 wavefront each
        float4 wa0 = *(const float4*)&g_edgeT[(size_t)e0 * T_DIM];
        float4 wb0 = *(const float4*)&g_edgeT[(size_t)e0 * T_DIM + 4];
        float4 wa1 = *(const float4*)&g_edgeT[(size_t)e1 * T_DIM];
        float4 wb1 = *(const float4*)&g_edgeT[(size_t)e1 * T_DIM + 4];
        int nin0 = idx_in_of(idx, e0, is64);
        int nin1 = idx_in_of(idx, e1, is64);
        float2 nv0 = *(const float2*)(node + (size_t)nin0 * 64 + lane * 2);
        float2 nv1 = *(const float2*)(node + (size_t)nin1 * 64 + lane * 2);
        float w0[8] = { wa0.x, wa0.y, wa0.z, wa0.w, wb0.x, wb0.y, wb0.z, wb0.w };
        float w1[8] = { wa1.x, wa1.y, wa1.z, wa1.w, wb1.x, wb1.y, wb1.z, wb1.w };
        #pragma unroll
        for (int t = 0; t < T_DIM; t++) {
            accx[t] += w0[t] * nv0.x + w1[t] * nv1.x;
            accy[t] += w0[t] * nv0.y + w1[t] * nv1.y;
        }
    }
    if (p < send) {
        int e = g_perm[p];
        float4 wa = *(const float4*)&g_edgeT[(size_t)e * T_DIM];
        float4 wb = *(const float4*)&g_edgeT[(size_t)e * T_DIM + 4];
        int nin = idx_in_of(idx, e, is64);
        float2 nv = *(const float2*)(node + (size_t)nin * 64 + lane * 2);
        float wv[8] = { wa.x, wa.y, wa.z, wa.w, wb.x, wb.y, wb.z, wb.w };
        #pragma unroll
        for (int t = 0; t < T_DIM; t++) {
            accx[t] += wv[t] * nv.x;
            accy[t] += wv[t] * nv.y;
        }
    }

    size_t base = (size_t)w * KDIM + lane * 2;
    #pragma unroll
    for (int t = 0; t < T_DIM; t++)
        *(float2*)&g_agg[base + t * 64] = make_float2(accx[t], accy[t]);
}

// ---------------- GEMM: out = agg(50000x512) @ W(512x64) + bias --------------
// FFMA2 inner product (R13-proven) + double-buffered smem with register
// prefetch: one __syncthreads per K-iter, gmem loads overlap compute.
#define BM 128
#define BN 64
#define BK 16
#define TM 8
#define TN 4
#define NKIT (KDIM / BK)   // 32

__global__ __launch_bounds__(256) void gemm_kernel(
    const float* __restrict__ W,      // (T*C, F) row-major
    const float* __restrict__ bias,
    float* __restrict__ out)
{
    __shared__ float As[2][BK][BM];   // 2 x 8 KB
    __shared__ float Bs[2][BK][BN];   // 2 x 4 KB

    const int tid  = threadIdx.x;
    const int row0 = blockIdx.x * BM;
    const int tx   = tid % 16;   // cols tx*4 .. tx*4+3
    const int ty   = tid / 16;   // rows ty*8 .. ty*8+7

    // A-tile load coords for this thread (2 float4s)
    const int r_a0  = (tid * 2) >> 2;
    const int c4_a0 = (tid * 2) & 3;
    const int r_a1  = (tid * 2 + 1) >> 2;
    const int c4_a1 = (tid * 2 + 1) & 3;
    const int kr_b  = tid >> 4;
    const int c4_b  = tid & 15;

    unsigned long long acc2[TM / 2][TN];
    #pragma unroll
    for (int i = 0; i < TM / 2; i++)
        #pragma unroll
        for (int j = 0; j < TN; j++) acc2[i][j] = 0ull;

    float4 pa0, pa1, pb;

    // prologue: load tile 0
    {
        pa0 = make_float4(0.f, 0.f, 0.f, 0.f);
        pa1 = pa0;
        if (row0 + r_a0 < N_OUT)
            pa0 = *(const float4*)&g_agg[(size_t)(row0 + r_a0) * KDIM + c4_a0 * 4];
        if (row0 + r_a1 < N_OUT)
            pa1 = *(const float4*)&g_agg[(size_t)(row0 + r_a1) * KDIM + c4_a1 * 4];
        pb = *(const float4*)&W[(size_t)kr_b * 64 + c4_b * 4];
    }
    // store tile 0 into buffer 0
    As[0][c4_a0 * 4 + 0][r_a0] = pa0.x;
    As[0][c4_a0 * 4 + 1][r_a0] = pa0.y;
    As[0][c4_a0 * 4 + 2][r_a0] = pa0.z;
    As[0][c4_a0 * 4 + 3][r_a0] = pa0.w;
    As[0][c4_a1 * 4 + 0][r_a1] = pa1.x;
    As[0][c4_a1 * 4 + 1][r_a1] = pa1.y;
    As[0][c4_a1 * 4 + 2][r_a1] = pa1.z;
    As[0][c4_a1 * 4 + 3][r_a1] = pa1.w;
    *(float4*)&Bs[0][kr_b][c4_b * 4] = pb;
    __syncthreads();

    for (int it = 0; it < NKIT; it++) {
        const int buf = it & 1;

        // prefetch next tile from gmem (overlaps with compute below)
        if (it + 1 < NKIT) {
            const int k0n = (it + 1) * BK;
            pa0 = make_float4(0.f, 0.f, 0.f, 0.f);
            pa1 = pa0;
            if (row0 + r_a0 < N_OUT)
                pa0 = *(const float4*)&g_agg[(size_t)(row0 + r_a0) * KDIM + k0n + c4_a0 * 4];
            if (row0 + r_a1 < N_OUT)
                pa1 = *(const float4*)&g_agg[(size_t)(row0 + r_a1) * KDIM + k0n + c4_a1 * 4];
            pb = *(const float4*)&W[(size_t)(k0n + kr_b) * 64 + c4_b * 4];
        }

        // compute on current buffer
        #pragma unroll
        for (int kk = 0; kk < BK; kk++) {
            ulonglong2 aq0 = *(const ulonglong2*)&As[buf][kk][ty * TM];
            ulonglong2 aq1 = *(const ulonglong2*)&As[buf][kk][ty * TM + 4];
            unsigned long long a2[4] = { aq0.x, aq0.y, aq1.x, aq1.y };
            float4 bq = *(const float4*)&Bs[buf][kk][tx * TN];
            unsigned long long b2[4];
            asm("mov.b64 %0, {%1, %1};" : "=l"(b2[0]) : "r"(__float_as_uint(bq.x)));
            asm("mov.b64 %0, {%1, %1};" : "=l"(b2[1]) : "r"(__float_as_uint(bq.y)));
            asm("mov.b64 %0, {%1, %1};" : "=l"(b2[2]) : "r"(__float_as_uint(bq.z)));
            asm("mov.b64 %0, {%1, %1};" : "=l"(b2[3]) : "r"(__float_as_uint(bq.w)));
            #pragma unroll
            for (int i = 0; i < 4; i++)
                #pragma unroll
                for (int j = 0; j < 4; j++)
                    asm("fma.rn.f32x2 %0, %1, %2, %0;"
                        : "+l"(acc2[i][j]) : "l"(a2[i]), "l"(b2[j]));
        }

        // stage next tile into the other buffer
        if (it + 1 < NKIT) {
            const int nb = buf ^ 1;
            As[nb][c4_a0 * 4 + 0][r_a0] = pa0.x;
            As[nb][c4_a0 * 4 + 1][r_a0] = pa0.y;
            As[nb][c4_a0 * 4 + 2][r_a0] = pa0.z;
            As[nb][c4_a0 * 4 + 3][r_a0] = pa0.w;
            As[nb][c4_a1 * 4 + 0][r_a1] = pa1.x;
            As[nb][c4_a1 * 4 + 1][r_a1] = pa1.y;
            As[nb][c4_a1 * 4 + 2][r_a1] = pa1.z;
            As[nb][c4_a1 * 4 + 3][r_a1] = pa1.w;
            *(float4*)&Bs[nb][kr_b][c4_b * 4] = pb;
        }
        __syncthreads();
    }

    float4 bv = *(const float4*)&bias[tx * TN];
    float bb[4] = { bv.x, bv.y, bv.z, bv.w };
    #pragma unroll
    for (int i = 0; i < TM / 2; i++) {
        int r0 = row0 + ty * TM + 2 * i;
        float lo[4], hi[4];
        #pragma unroll
        for (int j = 0; j < 4; j++) {
            unsigned int l, h;
            asm("mov.b64 {%0, %1}, %2;" : "=r"(l), "=r"(h) : "l"(acc2[i][j]));
            lo[j] = __uint_as_float(l) + bb[j];
            hi[j] = __uint_as_float(h) + bb[j];
        }
        if (r0 < N_OUT)
            *(float4*)&out[(size_t)r0 * F_DIM + tx * TN] = make_float4(lo[0], lo[1], lo[2], lo[3]);
        if (r0 + 1 < N_OUT)
            *(float4*)&out[(size_t)(r0 + 1) * F_DIM + tx * TN] = make_float4(hi[0], hi[1], hi[2], hi[3]);
    }
}

// ---------------- launch ----------------
extern "C" void kernel_launch(void* const* d_in, const int* in_sizes, int n_in,
                              void* d_out, int out_size)
{
    const float* node  = nullptr;
    const float* edgef = nullptr;
    const int*   idx   = nullptr;
    const float* W     = nullptr;
    const float* bias  = nullptr;

    for (int i = 0; i < n_in; i++) {
        switch (in_sizes[i]) {
            case N_IN * C_DIM:          node  = (const float*)d_in[i]; break;
            case T_DIM * E_EDGES:       edgef = (const float*)d_in[i]; break;
            case E_EDGES * 2:           idx   = (const int*)d_in[i];   break;
            case T_DIM * C_DIM * F_DIM: W     = (const float*)d_in[i]; break;
            case F_DIM:                 bias  = (const float*)d_in[i]; break;
            default: break;
        }
    }
    float* out = (float*)d_out;

    probe_kernel<<<1, 32>>>(idx);
    zero_counts_kernel<<<(N_OUT + 255) / 256, 256>>>();
    hist_transpose_kernel<<<(E_EDGES + 255) / 256, 256>>>(edgef, idx);
    scan_partial_kernel<<<SCAN_NBLK, SCAN_BLK>>>();
    scan_blocksums_kernel<<<1, 64>>>();
    scan_add_kernel<<<SCAN_NBLK, SCAN_BLK>>>();
    fill_perm_kernel<<<(E_EDGES + 255) / 256, 256>>>(idx);
    pull_kernel<<<N_OUT / 8, 256>>>(node, idx);
    gemm_kernel<<<(N_OUT + BM - 1) / BM, 256>>>(W, bias, out);
}